// round 12
// baseline (speedup 1.0000x reference)
#include <cuda_runtime.h>
#include <cuda_fp16.h>
#include <math.h>

#define IMG    416
#define N_ANG  320
#define N_DET  416
#define N_SAMP 416
#define PAD    244
#define PW     904                  // IMG + 2*PAD
#define NRAY   (N_ANG * N_DET)      // 133120

#define AGRP   2                    // angles per block
#define NAG    (N_ANG / AGRP)       // 160
#define TD     32                   // detectors per block (416 = 13*32, exact)
#define TS     64                   // samples per chunk
#define NDG    13                   // 416 / 32
#define NSC    7                    // ceil(416/64)
#define WIN    116                  // staged window (span needs ~105 + margins)
#define WSTR   120                  // word stride; mult of 4; 120 mod 32 = 24 shift
#define SMEM_BYTES (WIN * WSTR * 4) // 55,680 B -> 4 CTAs/SM
#define NBLK_R 520                  // NRAY / 256

// Scratch: packed image, g_padh[i] = half2( v[i], v[i+1 within row] )
__device__ __align__(16) __half2 g_padh[PW * PW];   // ~3.27 MB
__device__ float  g_part[NSC * NRAY];               // per-(chunk, ray) partials
__device__ double g_blk[NBLK_R];

// ---------------------------------------------------------------------------
// Kernel 1: diff + zero-pad + pack into half2 pixel pairs.
// ---------------------------------------------------------------------------
__device__ __forceinline__ float diffv(const float* in, const float* tgt,
                                       int r, int c) {
    int rr = r - PAD;
    int cc = c - PAD;
    if (rr >= 0 && rr < IMG && cc >= 0 && cc < IMG) {
        int j = rr * IMG + cc;
        return in[j] - tgt[j];
    }
    return 0.0f;
}

__global__ void pad_kernel(const float* __restrict__ in,
                           const float* __restrict__ tgt) {
    int i = blockIdx.x * blockDim.x + threadIdx.x;
    if (i >= PW * PW) return;
    int r = i / PW;
    int c = i - r * PW;
    g_padh[i] = __floats2half2_rn(diffv(in, tgt, r, c), diffv(in, tgt, r, c + 1));
}

// ---------------------------------------------------------------------------
// Kernel 2: SMEM-staged fan-beam projection.
// Block = (sample-chunk 64, det-group 32, angle-pair). 256 threads,
// 55.7 KB smem -> 4 CTAs/SM so staging overlaps compute across CTAs.
// Warp w (0..7): angle = ag*2 + (w & 1), det octet = w >> 1 in [0,3];
// lane = 8 dets x 4 sample-phases. 16 samples per thread.
// ---------------------------------------------------------------------------
__global__ void __launch_bounds__(256, 4) ray_kernel() {
    extern __shared__ __half2 smh[];
    __shared__ int sh_cmin, sh_rmin;

    const int chunk = blockIdx.x;   // 0..6
    const int dgrp  = blockIdx.y;   // 0..12
    const int ag    = blockIdx.z;   // 0..159
    const int tid   = threadIdx.x;

    const double hd_d   = 208.0 * sqrt(2.0);
    const double gmax_d = asin(hd_d / 1075.0);
    const float  THSTEP = (float)(2.0 * M_PI / 320.0);
    const float  GMAX   = (float)gmax_d;
    const float  DG     = (float)(2.0 * gmax_d / (N_DET - 1));
    const float  T0     = (float)(1075.0 - hd_d);
    const float  DTS    = (float)((2.0 * hd_d) / (N_SAMP - 1));
    const float  CTRP   = (float)((IMG - 1) * 0.5 + PAD);   // 451.5

    if (tid == 0) {
        int d_lo = dgrp * TD;
        int d_hi = d_lo + TD - 1;                  // always valid (13*32=416)
        int s_lo = chunk * TS;
        int s_hi = min(s_lo + TS - 1, N_SAMP - 1);
        float g_lo = fmaf((float)d_lo, DG, -GMAX);
        float g_hi = fmaf((float)d_hi, DG, -GMAX);
        float t_lo = fmaf((float)s_lo, DTS, T0);
        float t_hi = fmaf((float)s_hi, DTS, T0);

        float xmin = 1e30f, ymin = 1e30f;
        #pragma unroll
        for (int k = 0; k < AGRP; k++) {
            float th = (float)(ag * AGRP + k) * THSTEP;
            float sth, cth;
            sincosf(th, &sth, &cth);
            float bx = fmaf(1075.0f, cth, CTRP);
            float by = fmaf(1075.0f, sth, CTRP);
            float s1, c1, s2, c2;
            sincosf(th + g_lo, &s1, &c1);
            sincosf(th + g_hi, &s2, &c2);
            xmin = fminf(xmin, fminf(fminf(fmaf(-t_lo, c1, bx), fmaf(-t_hi, c1, bx)),
                                     fminf(fmaf(-t_lo, c2, bx), fmaf(-t_hi, c2, bx))));
            ymin = fminf(ymin, fminf(fminf(fmaf(-t_lo, s1, by), fmaf(-t_hi, s1, by)),
                                     fminf(fmaf(-t_lo, s2, by), fmaf(-t_hi, s2, by))));
        }

        int cmin = (int)floorf(xmin) - 2;
        int rmin = (int)floorf(ymin) - 2;
        sh_cmin = max(0, min(cmin, PW - WIN)) & ~3;   // 16B-aligned for uint4
        sh_rmin = max(0, min(rmin, PW - WIN));
    }
    __syncthreads();

    const int cmin = sh_cmin;
    const int rmin = sh_rmin;

    // stage WIN x WIN half2 words via uint4 (4 words = 16 B; WIN/4 = 29)
    {
        const uint4* __restrict__ src =
            (const uint4*)(g_padh + rmin * PW + cmin);
        uint4* dst = (uint4*)smh;
        #pragma unroll 4
        for (int idx = tid; idx < WIN * (WIN / 4); idx += 256) {
            int rr = idx / (WIN / 4);
            int cc = idx - rr * (WIN / 4);
            dst[rr * (WSTR / 4) + cc] = src[rr * (PW / 4) + cc];
        }
    }
    __syncthreads();

    // compute
    const int warp   = tid >> 5;
    const int lane   = tid & 31;
    const int a      = ag * AGRP + (warp & 1);
    const int det    = dgrp * TD + (warp >> 1) * 8 + (lane >> 2);
    const int sphase = lane & 3;

    float acc = 0.0f;
    {
        const float theta = (float)a * THSTEP;
        float sth, cth;
        sincosf(theta, &sth, &cth);
        const float gamma = fmaf((float)det, DG, -GMAX);
        float sph, cph;
        sincosf(theta + gamma, &sph, &cph);

        const float bxl  = fmaf(1075.0f, cth, CTRP) - (float)cmin;
        const float byl  = fmaf(1075.0f, sth, CTRP) - (float)rmin;
        const float ncph = -cph;
        const float nsph = -sph;

        const int s_base = chunk * TS + sphase;
        const int niter  = (chunk == NSC - 1) ? 8 : 16;  // last chunk: 32 samples

        #pragma unroll 8
        for (int i = 0; i < niter; i++) {
            float t  = fmaf((float)(s_base + 4 * i), DTS, T0);
            float x  = fmaf(t, ncph, bxl);
            float y  = fmaf(t, nsph, byl);
            float fx = floorf(x);
            float fy = floorf(y);
            float wc = x - fx;
            float wr = y - fy;
            int addr = (int)fy * WSTR + (int)fx;
            float2 tp = __half22float2(smh[addr]);          // (v00, v01)
            float2 bt = __half22float2(smh[addr + WSTR]);   // (v10, v11)
            float top = fmaf(wc, tp.y - tp.x, tp.x);
            float bot = fmaf(wc, bt.y - bt.x, bt.x);
            acc = fmaf(wr, bot - top, acc + top);
        }
    }

    // reduce 4 phases per detector
    acc += __shfl_xor_sync(0xFFFFFFFFu, acc, 1);
    acc += __shfl_xor_sync(0xFFFFFFFFu, acc, 2);

    if (sphase == 0) {
        g_part[chunk * NRAY + a * N_DET + det] = acc;
    }
}

// ---------------------------------------------------------------------------
// Kernel 3a: per-ray chunk sum + square, per-block tree reduce (double).
// ---------------------------------------------------------------------------
__global__ void raysum_kernel() {
    __shared__ double smr[256];
    const double hd_d = 208.0 * sqrt(2.0);
    const float  DTS  = (float)((2.0 * hd_d) / (N_SAMP - 1));
    int tid = threadIdx.x;
    int ray = blockIdx.x * 256 + tid;

    float v = 0.0f;
    #pragma unroll
    for (int s = 0; s < NSC; s++)
        v += g_part[s * NRAY + ray];
    float val = v * DTS;
    smr[tid] = (double)val * (double)val;
    __syncthreads();
    for (int stride = 128; stride > 0; stride >>= 1) {
        if (tid < stride) smr[tid] += smr[tid + stride];
        __syncthreads();
    }
    if (tid == 0) g_blk[blockIdx.x] = smr[0];
}

// ---------------------------------------------------------------------------
// Kernel 3b: final deterministic reduction -> mean * SCALE.
// ---------------------------------------------------------------------------
__global__ void reduce_kernel(float* __restrict__ out) {
    __shared__ double smr[1024];
    int tid = threadIdx.x;
    smr[tid] = (tid < NBLK_R) ? g_blk[tid] : 0.0;
    __syncthreads();
    for (int stride = 512; stride > 0; stride >>= 1) {
        if (tid < stride) smr[tid] += smr[tid + stride];
        __syncthreads();
    }
    if (tid == 0) {
        const double SCALE = 512.0 / 416.0 * 0.03;
        out[0] = (float)(smr[0] / (double)NRAY * SCALE);
    }
}

// ---------------------------------------------------------------------------
extern "C" void kernel_launch(void* const* d_in, const int* in_sizes, int n_in,
                              void* d_out, int out_size) {
    const float* in  = (const float*)d_in[0];
    const float* tgt = (const float*)d_in[1];
    float* out = (float*)d_out;
    (void)in_sizes; (void)n_in; (void)out_size;

    static int configured = 0;
    if (!configured) {
        cudaFuncSetAttribute(ray_kernel,
                             cudaFuncAttributeMaxDynamicSharedMemorySize,
                             SMEM_BYTES);
        configured = 1;
    }

    pad_kernel<<<(PW * PW + 255) / 256, 256>>>(in, tgt);
    ray_kernel<<<dim3(NSC, NDG, NAG), 256, SMEM_BYTES>>>();
    raysum_kernel<<<NBLK_R, 256>>>();
    reduce_kernel<<<1, 1024>>>(out);
}

// round 13
// speedup vs baseline: 1.6244x; 1.6244x over previous
#include <cuda_runtime.h>
#include <cuda_fp16.h>
#include <math.h>

#define IMG    416
#define N_ANG  320
#define N_DET  416
#define N_SAMP 416
#define PAD    244
#define PW     904                  // IMG + 2*PAD
#define NRAY   (N_ANG * N_DET)      // 133120

#define AGRP   2                    // angles per block
#define NAG    (N_ANG / AGRP)       // 160
#define TD     64                   // detectors per block
#define TS     64                   // samples per chunk
#define NDG    7                    // ceil(416/64)
#define NSC    7                    // ceil(416/64)
#define WIN    168                  // staged window (span <= ~146 + margins 7)
#define WSTR   172                  // word stride; mult of 4; 172 mod 32 = 12
#define SMEM_BYTES (WIN * WSTR * 4) // 115,584 B -> 2 CTAs/SM
#define NBLK_R 520                  // NRAY / 256

// Scratch: packed image, g_padh[i] = half2( v[i], v[i+1 within row] )
__device__ __align__(16) __half2 g_padh[PW * PW];   // ~3.27 MB
__device__ float  g_part[NRAY];                     // per-ray projection sum
__device__ double g_blk[NBLK_R];

// ---------------------------------------------------------------------------
// Kernel 1: diff + zero-pad + pack into half2 pixel pairs.
// ---------------------------------------------------------------------------
__device__ __forceinline__ float diffv(const float* in, const float* tgt,
                                       int r, int c) {
    int rr = r - PAD;
    int cc = c - PAD;
    if (rr >= 0 && rr < IMG && cc >= 0 && cc < IMG) {
        int j = rr * IMG + cc;
        return in[j] - tgt[j];
    }
    return 0.0f;
}

__global__ void pad_kernel(const float* __restrict__ in,
                           const float* __restrict__ tgt) {
    int i = blockIdx.x * blockDim.x + threadIdx.x;
    if (i >= PW * PW) return;
    int r = i / PW;
    int c = i - r * PW;
    g_padh[i] = __floats2half2_rn(diffv(in, tgt, r, c), diffv(in, tgt, r, c + 1));
}

// ---------------------------------------------------------------------------
// Kernel 2: SMEM-staged fan-beam projection, chunk loop inside the block.
// Block = (det-group 64, angle-pair); 512 threads; 2 CTAs/SM.
// Per chunk: uniform register bbox -> sync -> warp-row staged window -> sync
// -> 16 bilinear samples per thread (identical inner loop to R11).
// Warp w (0..15): angle = ag*2 + (w & 1), det octet = w >> 1 in [0,7].
// ---------------------------------------------------------------------------
__global__ void __launch_bounds__(512, 2) ray_kernel() {
    extern __shared__ __half2 smh[];

    const int dgrp = blockIdx.x;    // 0..6
    const int ag   = blockIdx.y;    // 0..159
    const int tid  = threadIdx.x;

    const double hd_d   = 208.0 * sqrt(2.0);
    const double gmax_d = asin(hd_d / 1075.0);
    const float  THSTEP = (float)(2.0 * M_PI / 320.0);
    const float  GMAX   = (float)gmax_d;
    const float  DG     = (float)(2.0 * gmax_d / (N_DET - 1));
    const float  T0     = (float)(1075.0 - hd_d);
    const float  DTS    = (float)((2.0 * hd_d) / (N_SAMP - 1));
    const float  CTRP   = (float)((IMG - 1) * 0.5 + PAD);   // 451.5

    // ---- per-block geometry (uniform across threads, registers) ----
    const int   d_lo = dgrp * TD;
    const int   d_hi = min(d_lo + TD - 1, N_DET - 1);
    const float g_lo = fmaf((float)d_lo, DG, -GMAX);
    const float g_hi = fmaf((float)d_hi, DG, -GMAX);

    float bxk[2], byk[2], ck[4], sk[4];
    #pragma unroll
    for (int k = 0; k < AGRP; k++) {
        float th = (float)(ag * AGRP + k) * THSTEP;
        float sth, cth;
        sincosf(th, &sth, &cth);
        bxk[k] = fmaf(1075.0f, cth, CTRP);
        byk[k] = fmaf(1075.0f, sth, CTRP);
        sincosf(th + g_lo, &sk[k * 2 + 0], &ck[k * 2 + 0]);
        sincosf(th + g_hi, &sk[k * 2 + 1], &ck[k * 2 + 1]);
    }

    // ---- per-thread ray constants ----
    const int warp   = tid >> 5;
    const int lane   = tid & 31;
    const int ak     = warp & 1;
    const int a      = ag * AGRP + ak;
    const int det    = dgrp * TD + (warp >> 1) * 8 + (lane >> 2);
    const int sphase = lane & 3;
    const bool valid = (det < N_DET);

    float ncph = 0.0f, nsph = 0.0f;
    if (valid) {
        const float theta = (float)a * THSTEP;
        const float gamma = fmaf((float)det, DG, -GMAX);
        float sph, cph;
        sincosf(theta + gamma, &sph, &cph);
        ncph = -cph;
        nsph = -sph;
    }

    float acc = 0.0f;

    #pragma unroll 1
    for (int c = 0; c < NSC; c++) {
        // ---- bbox for this chunk: pure fma on cached corner sin/cos ----
        const int s_lo = c * TS;
        const int s_hi = min(s_lo + TS - 1, N_SAMP - 1);
        const float t_lo = fmaf((float)s_lo, DTS, T0);
        const float t_hi = fmaf((float)s_hi, DTS, T0);

        float xmin = 1e30f, ymin = 1e30f;
        #pragma unroll
        for (int k = 0; k < AGRP; k++) {
            #pragma unroll
            for (int j = 0; j < 2; j++) {
                float cc = ck[k * 2 + j], ss = sk[k * 2 + j];
                xmin = fminf(xmin, fminf(fmaf(-t_lo, cc, bxk[k]), fmaf(-t_hi, cc, bxk[k])));
                ymin = fminf(ymin, fminf(fmaf(-t_lo, ss, byk[k]), fmaf(-t_hi, ss, byk[k])));
            }
        }
        const int cmin = (max(0, min((int)floorf(xmin) - 2, PW - WIN))) & ~3;
        const int rmin =  max(0, min((int)floorf(ymin) - 2, PW - WIN));

        __syncthreads();   // previous chunk's reads complete before overwrite

        // ---- stage WIN x WIN half2 words via uint4; warp-row layout ----
        {
            const uint4* __restrict__ src =
                (const uint4*)(g_padh + rmin * PW + cmin);
            uint4* dst = (uint4*)smh;
            for (int rr = warp; rr < WIN; rr += 16) {
                #pragma unroll
                for (int cc = lane; cc < WIN / 4; cc += 32) {
                    dst[rr * (WSTR / 4) + cc] = src[rr * (PW / 4) + cc];
                }
            }
        }
        __syncthreads();

        // ---- compute 16 samples (identical to R11 inner loop) ----
        if (valid) {
            const float bxl = bxk[ak] - (float)cmin;
            const float byl = byk[ak] - (float)rmin;
            const int s_base = c * TS + sphase;
            const int niter  = (c == NSC - 1) ? 8 : 16;

            #pragma unroll 8
            for (int i = 0; i < niter; i++) {
                float t  = fmaf((float)(s_base + 4 * i), DTS, T0);
                float x  = fmaf(t, ncph, bxl);
                float y  = fmaf(t, nsph, byl);
                float fx = floorf(x);
                float fy = floorf(y);
                float wc = x - fx;
                float wr = y - fy;
                int addr = (int)fy * WSTR + (int)fx;
                float2 tp = __half22float2(smh[addr]);          // (v00, v01)
                float2 bt = __half22float2(smh[addr + WSTR]);   // (v10, v11)
                float top = fmaf(wc, tp.y - tp.x, tp.x);
                float bot = fmaf(wc, bt.y - bt.x, bt.x);
                acc = fmaf(wr, bot - top, acc + top);
            }
        }
    }

    // reduce 4 phases per detector
    acc += __shfl_xor_sync(0xFFFFFFFFu, acc, 1);
    acc += __shfl_xor_sync(0xFFFFFFFFu, acc, 2);

    if (sphase == 0 && valid) {
        g_part[a * N_DET + det] = acc;
    }
}

// ---------------------------------------------------------------------------
// Kernel 3a: square per ray, per-block tree reduce (double).
// ---------------------------------------------------------------------------
__global__ void raysum_kernel() {
    __shared__ double smr[256];
    const double hd_d = 208.0 * sqrt(2.0);
    const float  DTS  = (float)((2.0 * hd_d) / (N_SAMP - 1));
    int tid = threadIdx.x;
    int ray = blockIdx.x * 256 + tid;

    float val = g_part[ray] * DTS;
    smr[tid] = (double)val * (double)val;
    __syncthreads();
    for (int stride = 128; stride > 0; stride >>= 1) {
        if (tid < stride) smr[tid] += smr[tid + stride];
        __syncthreads();
    }
    if (tid == 0) g_blk[blockIdx.x] = smr[0];
}

// ---------------------------------------------------------------------------
// Kernel 3b: final deterministic reduction -> mean * SCALE.
// ---------------------------------------------------------------------------
__global__ void reduce_kernel(float* __restrict__ out) {
    __shared__ double smr[1024];
    int tid = threadIdx.x;
    smr[tid] = (tid < NBLK_R) ? g_blk[tid] : 0.0;
    __syncthreads();
    for (int stride = 512; stride > 0; stride >>= 1) {
        if (tid < stride) smr[tid] += smr[tid + stride];
        __syncthreads();
    }
    if (tid == 0) {
        const double SCALE = 512.0 / 416.0 * 0.03;
        out[0] = (float)(smr[0] / (double)NRAY * SCALE);
    }
}

// ---------------------------------------------------------------------------
extern "C" void kernel_launch(void* const* d_in, const int* in_sizes, int n_in,
                              void* d_out, int out_size) {
    const float* in  = (const float*)d_in[0];
    const float* tgt = (const float*)d_in[1];
    float* out = (float*)d_out;
    (void)in_sizes; (void)n_in; (void)out_size;

    static int configured = 0;
    if (!configured) {
        cudaFuncSetAttribute(ray_kernel,
                             cudaFuncAttributeMaxDynamicSharedMemorySize,
                             SMEM_BYTES);
        configured = 1;
    }

    pad_kernel<<<(PW * PW + 255) / 256, 256>>>(in, tgt);
    ray_kernel<<<dim3(NDG, NAG), 512, SMEM_BYTES>>>();
    raysum_kernel<<<NBLK_R, 256>>>();
    reduce_kernel<<<1, 1024>>>(out);
}

// round 14
// speedup vs baseline: 1.9484x; 1.1995x over previous
#include <cuda_runtime.h>
#include <cuda_fp16.h>
#include <math.h>

#define IMG    416
#define N_ANG  320
#define N_DET  416
#define N_SAMP 416
#define PAD    244
#define PW     904                  // IMG + 2*PAD
#define NRAY   (N_ANG * N_DET)      // 133120

#define AGRP   2                    // angles per block
#define NAG    (N_ANG / AGRP)       // 160
#define TD     64                   // detectors per block
#define TS     64                   // samples per chunk
#define NDG    7                    // ceil(416/64)
#define NSC    7                    // ceil(416/64)
#define WIN    168                  // staged window (span <= ~146 + margins 7)
#define WSTR   172                  // word stride; mult of 4; 172 mod 32 = 12
#define SMEM_BYTES (WIN * WSTR * 4) // 115,584 B -> 2 CTAs/SM
#define NBLK_R 520                  // NRAY / 256

// Scratch: packed image, g_padh[i] = half2( v[i], v[i+1 within row] )
__device__ __align__(16) __half2 g_padh[PW * PW];   // ~3.27 MB
__device__ float  g_part[NRAY];                     // per-ray projection sum
__device__ double g_blk[NBLK_R];

// ---------------------------------------------------------------------------
// Kernel 1: diff + zero-pad + pack into half2 pixel pairs.
// ---------------------------------------------------------------------------
__device__ __forceinline__ float diffv(const float* in, const float* tgt,
                                       int r, int c) {
    int rr = r - PAD;
    int cc = c - PAD;
    if (rr >= 0 && rr < IMG && cc >= 0 && cc < IMG) {
        int j = rr * IMG + cc;
        return in[j] - tgt[j];
    }
    return 0.0f;
}

__global__ void pad_kernel(const float* __restrict__ in,
                           const float* __restrict__ tgt) {
    int i = blockIdx.x * blockDim.x + threadIdx.x;
    if (i >= PW * PW) return;
    int r = i / PW;
    int c = i - r * PW;
    g_padh[i] = __floats2half2_rn(diffv(in, tgt, r, c), diffv(in, tgt, r, c + 1));
}

// ---------------------------------------------------------------------------
// Kernel 2: SMEM-staged fan-beam projection, chunk loop inside the block,
// with block-uniform skip of chunks whose sample bbox misses the image.
// Block = (det-group 64, angle-pair); 512 threads; 2 CTAs/SM.
// Warp w (0..15): angle = ag*2 + (w & 1), det octet = w >> 1 in [0,7].
// ---------------------------------------------------------------------------
__global__ void __launch_bounds__(512, 2) ray_kernel() {
    extern __shared__ __half2 smh[];

    const int dgrp = blockIdx.x;    // 0..6
    const int ag   = blockIdx.y;    // 0..159
    const int tid  = threadIdx.x;

    const double hd_d   = 208.0 * sqrt(2.0);
    const double gmax_d = asin(hd_d / 1075.0);
    const float  THSTEP = (float)(2.0 * M_PI / 320.0);
    const float  GMAX   = (float)gmax_d;
    const float  DG     = (float)(2.0 * gmax_d / (N_DET - 1));
    const float  T0     = (float)(1075.0 - hd_d);
    const float  DTS    = (float)((2.0 * hd_d) / (N_SAMP - 1));
    const float  CTRP   = (float)((IMG - 1) * 0.5 + PAD);   // 451.5

    // ---- per-block geometry (uniform across threads, registers) ----
    const int   d_lo = dgrp * TD;
    const int   d_hi = min(d_lo + TD - 1, N_DET - 1);
    const float g_lo = fmaf((float)d_lo, DG, -GMAX);
    const float g_hi = fmaf((float)d_hi, DG, -GMAX);

    float bxk[2], byk[2], ck[4], sk[4];
    #pragma unroll
    for (int k = 0; k < AGRP; k++) {
        float th = (float)(ag * AGRP + k) * THSTEP;
        float sth, cth;
        sincosf(th, &sth, &cth);
        bxk[k] = fmaf(1075.0f, cth, CTRP);
        byk[k] = fmaf(1075.0f, sth, CTRP);
        sincosf(th + g_lo, &sk[k * 2 + 0], &ck[k * 2 + 0]);
        sincosf(th + g_hi, &sk[k * 2 + 1], &ck[k * 2 + 1]);
    }

    // ---- per-thread ray constants ----
    const int warp   = tid >> 5;
    const int lane   = tid & 31;
    const int ak     = warp & 1;
    const int a      = ag * AGRP + ak;
    const int det    = dgrp * TD + (warp >> 1) * 8 + (lane >> 2);
    const int sphase = lane & 3;
    const bool valid = (det < N_DET);

    float ncph = 0.0f, nsph = 0.0f;
    if (valid) {
        const float theta = (float)a * THSTEP;
        const float gamma = fmaf((float)det, DG, -GMAX);
        float sph, cph;
        sincosf(theta + gamma, &sph, &cph);
        ncph = -cph;
        nsph = -sph;
    }

    float acc = 0.0f;

    #pragma unroll 1
    for (int c = 0; c < NSC; c++) {
        // ---- bbox for this chunk: pure fma on cached corner sin/cos ----
        const int s_lo = c * TS;
        const int s_hi = min(s_lo + TS - 1, N_SAMP - 1);
        const float t_lo = fmaf((float)s_lo, DTS, T0);
        const float t_hi = fmaf((float)s_hi, DTS, T0);

        float xmin = 1e30f, ymin = 1e30f;
        float xmax = -1e30f, ymax = -1e30f;
        #pragma unroll
        for (int k = 0; k < AGRP; k++) {
            #pragma unroll
            for (int j = 0; j < 2; j++) {
                float cc = ck[k * 2 + j], ss = sk[k * 2 + j];
                float x0 = fmaf(-t_lo, cc, bxk[k]);
                float x1 = fmaf(-t_hi, cc, bxk[k]);
                float y0 = fmaf(-t_lo, ss, byk[k]);
                float y1 = fmaf(-t_hi, ss, byk[k]);
                xmin = fminf(xmin, fminf(x0, x1));
                xmax = fmaxf(xmax, fmaxf(x0, x1));
                ymin = fminf(ymin, fminf(y0, y1));
                ymax = fmaxf(ymax, fmaxf(y0, y1));
            }
        }

        // ---- skip chunks that cannot touch the nonzero image square ----
        // image pixels live at [PAD, PAD+IMG); bilinear support 1 px;
        // arc bulge beyond corner bbox < 1.3 px; margin 3 covers both.
        if (xmax < (float)(PAD - 3) || xmin > (float)(PAD + IMG + 2) ||
            ymax < (float)(PAD - 3) || ymin > (float)(PAD + IMG + 2))
            continue;   // uniform across block: barriers stay uniform

        const int cmin = (max(0, min((int)floorf(xmin) - 2, PW - WIN))) & ~3;
        const int rmin =  max(0, min((int)floorf(ymin) - 2, PW - WIN));

        __syncthreads();   // previous chunk's reads complete before overwrite

        // ---- stage WIN x WIN half2 words via uint4; warp-row layout ----
        {
            const uint4* __restrict__ src =
                (const uint4*)(g_padh + rmin * PW + cmin);
            uint4* dst = (uint4*)smh;
            for (int rr = warp; rr < WIN; rr += 16) {
                #pragma unroll
                for (int cc = lane; cc < WIN / 4; cc += 32) {
                    dst[rr * (WSTR / 4) + cc] = src[rr * (PW / 4) + cc];
                }
            }
        }
        __syncthreads();

        // ---- compute 16 samples (identical to R13 inner loop) ----
        if (valid) {
            const float bxl = bxk[ak] - (float)cmin;
            const float byl = byk[ak] - (float)rmin;
            const int s_base = c * TS + sphase;
            const int niter  = (c == NSC - 1) ? 8 : 16;

            #pragma unroll 8
            for (int i = 0; i < niter; i++) {
                float t  = fmaf((float)(s_base + 4 * i), DTS, T0);
                float x  = fmaf(t, ncph, bxl);
                float y  = fmaf(t, nsph, byl);
                float fx = floorf(x);
                float fy = floorf(y);
                float wc = x - fx;
                float wr = y - fy;
                int addr = (int)fy * WSTR + (int)fx;
                float2 tp = __half22float2(smh[addr]);          // (v00, v01)
                float2 bt = __half22float2(smh[addr + WSTR]);   // (v10, v11)
                float top = fmaf(wc, tp.y - tp.x, tp.x);
                float bot = fmaf(wc, bt.y - bt.x, bt.x);
                acc = fmaf(wr, bot - top, acc + top);
            }
        }
    }

    // reduce 4 phases per detector
    acc += __shfl_xor_sync(0xFFFFFFFFu, acc, 1);
    acc += __shfl_xor_sync(0xFFFFFFFFu, acc, 2);

    if (sphase == 0 && valid) {
        g_part[a * N_DET + det] = acc;
    }
}

// ---------------------------------------------------------------------------
// Kernel 3a: square per ray, per-block tree reduce (double).
// ---------------------------------------------------------------------------
__global__ void raysum_kernel() {
    __shared__ double smr[256];
    const double hd_d = 208.0 * sqrt(2.0);
    const float  DTS  = (float)((2.0 * hd_d) / (N_SAMP - 1));
    int tid = threadIdx.x;
    int ray = blockIdx.x * 256 + tid;

    float val = g_part[ray] * DTS;
    smr[tid] = (double)val * (double)val;
    __syncthreads();
    for (int stride = 128; stride > 0; stride >>= 1) {
        if (tid < stride) smr[tid] += smr[tid + stride];
        __syncthreads();
    }
    if (tid == 0) g_blk[blockIdx.x] = smr[0];
}

// ---------------------------------------------------------------------------
// Kernel 3b: final deterministic reduction -> mean * SCALE.
// ---------------------------------------------------------------------------
__global__ void reduce_kernel(float* __restrict__ out) {
    __shared__ double smr[1024];
    int tid = threadIdx.x;
    smr[tid] = (tid < NBLK_R) ? g_blk[tid] : 0.0;
    __syncthreads();
    for (int stride = 512; stride > 0; stride >>= 1) {
        if (tid < stride) smr[tid] += smr[tid + stride];
        __syncthreads();
    }
    if (tid == 0) {
        const double SCALE = 512.0 / 416.0 * 0.03;
        out[0] = (float)(smr[0] / (double)NRAY * SCALE);
    }
}

// ---------------------------------------------------------------------------
extern "C" void kernel_launch(void* const* d_in, const int* in_sizes, int n_in,
                              void* d_out, int out_size) {
    const float* in  = (const float*)d_in[0];
    const float* tgt = (const float*)d_in[1];
    float* out = (float*)d_out;
    (void)in_sizes; (void)n_in; (void)out_size;

    static int configured = 0;
    if (!configured) {
        cudaFuncSetAttribute(ray_kernel,
                             cudaFuncAttributeMaxDynamicSharedMemorySize,
                             SMEM_BYTES);
        configured = 1;
    }

    pad_kernel<<<(PW * PW + 255) / 256, 256>>>(in, tgt);
    ray_kernel<<<dim3(NDG, NAG), 512, SMEM_BYTES>>>();
    raysum_kernel<<<NBLK_R, 256>>>();
    reduce_kernel<<<1, 1024>>>(out);
}

// round 15
// speedup vs baseline: 2.3694x; 1.2161x over previous
#include <cuda_runtime.h>
#include <cuda_fp16.h>
#include <math.h>

#define IMG    416
#define N_ANG  320
#define N_DET  416
#define N_SAMP 416
#define PAD    244
#define PW     904                  // IMG + 2*PAD
#define NRAY   (N_ANG * N_DET)      // 133120

#define AGRP   4                    // angles per block
#define NAG    (N_ANG / AGRP)       // 80
#define TD     32                   // detectors per block (416 = 13*32, exact)
#define TS     64                   // samples per chunk
#define NDG    13                   // 416 / 32
#define NSC    7                    // ceil(416/64)
#define WIN    144                  // staged window (span <= ~139.4)
#define WSTR   148                  // word stride; mult of 4; 148 mod 32 = 20
#define SMEM_BYTES (WIN * WSTR * 4) // 85,248 B -> 2 CTAs/SM
#define NBLK_R 520                  // NRAY / 256

// Scratch: packed image, g_padh[i] = half2( v[i], v[i+1 within row] )
__device__ __align__(16) __half2 g_padh[PW * PW];   // ~3.27 MB
__device__ float  g_part[NRAY];                     // per-ray projection sum
__device__ double g_blk[NBLK_R];

// ---------------------------------------------------------------------------
// Kernel 1: diff + zero-pad + pack into half2 pixel pairs.
// ---------------------------------------------------------------------------
__device__ __forceinline__ float diffv(const float* in, const float* tgt,
                                       int r, int c) {
    int rr = r - PAD;
    int cc = c - PAD;
    if (rr >= 0 && rr < IMG && cc >= 0 && cc < IMG) {
        int j = rr * IMG + cc;
        return in[j] - tgt[j];
    }
    return 0.0f;
}

__global__ void pad_kernel(const float* __restrict__ in,
                           const float* __restrict__ tgt) {
    int i = blockIdx.x * blockDim.x + threadIdx.x;
    if (i >= PW * PW) return;
    int r = i / PW;
    int c = i - r * PW;
    g_padh[i] = __floats2half2_rn(diffv(in, tgt, r, c), diffv(in, tgt, r, c + 1));
}

// ---------------------------------------------------------------------------
// Kernel 2: SMEM-staged fan-beam projection; 4 angles x 32 dets per block,
// chunk loop inside, block-uniform skip of all-zero chunks.
// 512 threads; 2 CTAs/SM. Warp w (0..15): angle = ag*4 + (w & 3),
// det octet = w >> 2 in [0,3]; lane = 8 dets x 4 phases. All rays valid.
// ---------------------------------------------------------------------------
__global__ void __launch_bounds__(512, 2) ray_kernel() {
    extern __shared__ __half2 smh[];

    const int dgrp = blockIdx.x;    // 0..12
    const int ag   = blockIdx.y;    // 0..79
    const int tid  = threadIdx.x;

    const double hd_d   = 208.0 * sqrt(2.0);
    const double gmax_d = asin(hd_d / 1075.0);
    const float  THSTEP = (float)(2.0 * M_PI / 320.0);
    const float  GMAX   = (float)gmax_d;
    const float  DG     = (float)(2.0 * gmax_d / (N_DET - 1));
    const float  T0     = (float)(1075.0 - hd_d);
    const float  DTS    = (float)((2.0 * hd_d) / (N_SAMP - 1));
    const float  CTRP   = (float)((IMG - 1) * 0.5 + PAD);   // 451.5

    // ---- per-block geometry (uniform across threads, registers) ----
    const float g_lo = fmaf((float)(dgrp * TD), DG, -GMAX);
    const float g_hi = fmaf((float)(dgrp * TD + TD - 1), DG, -GMAX);

    // source-center for all 4 angles (compute path)
    float bxa[4], bya[4];
    #pragma unroll
    for (int k = 0; k < AGRP; k++) {
        float th = (float)(ag * AGRP + k) * THSTEP;
        float sth, cth;
        sincosf(th, &sth, &cth);
        bxa[k] = fmaf(1075.0f, cth, CTRP);
        bya[k] = fmaf(1075.0f, sth, CTRP);
    }
    // corner-ray direction cos/sin for the two EXTREME angles (bbox path);
    // intermediate angles deviate < 0.2 px (chord sagitta), inside margins.
    float ckc[4], skc[4];
    #pragma unroll
    for (int e = 0; e < 2; e++) {
        float th = (float)(ag * AGRP + e * (AGRP - 1)) * THSTEP;
        sincosf(th + g_lo, &skc[e * 2 + 0], &ckc[e * 2 + 0]);
        sincosf(th + g_hi, &skc[e * 2 + 1], &ckc[e * 2 + 1]);
    }

    // ---- per-thread ray constants ----
    const int warp   = tid >> 5;
    const int lane   = tid & 31;
    const int ak     = warp & 3;                // angle within group
    const int a      = ag * AGRP + ak;
    const int det    = dgrp * TD + (warp >> 2) * 8 + (lane >> 2);
    const int sphase = lane & 3;

    float ncph, nsph;
    {
        const float theta = (float)a * THSTEP;
        const float gamma = fmaf((float)det, DG, -GMAX);
        float sph, cph;
        sincosf(theta + gamma, &sph, &cph);
        ncph = -cph;
        nsph = -sph;
    }

    float acc = 0.0f;

    #pragma unroll 1
    for (int c = 0; c < NSC; c++) {
        // ---- bbox for this chunk (extreme angles' corner rays) ----
        const int s_lo = c * TS;
        const int s_hi = min(s_lo + TS - 1, N_SAMP - 1);
        const float t_lo = fmaf((float)s_lo, DTS, T0);
        const float t_hi = fmaf((float)s_hi, DTS, T0);

        float xmin = 1e30f, ymin = 1e30f;
        float xmax = -1e30f, ymax = -1e30f;
        #pragma unroll
        for (int e = 0; e < 2; e++) {
            const float bxe = bxa[e * (AGRP - 1)];
            const float bye = bya[e * (AGRP - 1)];
            #pragma unroll
            for (int j = 0; j < 2; j++) {
                float cc = ckc[e * 2 + j], ss = skc[e * 2 + j];
                float x0 = fmaf(-t_lo, cc, bxe);
                float x1 = fmaf(-t_hi, cc, bxe);
                float y0 = fmaf(-t_lo, ss, bye);
                float y1 = fmaf(-t_hi, ss, bye);
                xmin = fminf(xmin, fminf(x0, x1));
                xmax = fmaxf(xmax, fmaxf(x0, x1));
                ymin = fminf(ymin, fminf(y0, y1));
                ymax = fmaxf(ymax, fmaxf(y0, y1));
            }
        }

        // ---- skip chunks that cannot touch the nonzero image square ----
        if (xmax < (float)(PAD - 3) || xmin > (float)(PAD + IMG + 2) ||
            ymax < (float)(PAD - 3) || ymin > (float)(PAD + IMG + 2))
            continue;   // uniform across block: barriers stay uniform

        const int cmin = (max(0, min((int)floorf(xmin) - 2, PW - WIN))) & ~3;
        const int rmin =  max(0, min((int)floorf(ymin) - 2, PW - WIN));

        __syncthreads();   // previous chunk's reads complete before overwrite

        // ---- stage WIN x WIN half2 words via uint4; warp-row layout ----
        {
            const uint4* __restrict__ src =
                (const uint4*)(g_padh + rmin * PW + cmin);
            uint4* dst = (uint4*)smh;
            for (int rr = warp; rr < WIN; rr += 16) {
                #pragma unroll
                for (int cc = lane; cc < WIN / 4; cc += 32) {
                    dst[rr * (WSTR / 4) + cc] = src[rr * (PW / 4) + cc];
                }
            }
        }
        __syncthreads();

        // ---- compute 16 samples (identical inner loop to R14) ----
        {
            const float bxl = bxa[ak] - (float)cmin;
            const float byl = bya[ak] - (float)rmin;
            const int s_base = c * TS + sphase;
            const int niter  = (c == NSC - 1) ? 8 : 16;

            #pragma unroll 8
            for (int i = 0; i < niter; i++) {
                float t  = fmaf((float)(s_base + 4 * i), DTS, T0);
                float x  = fmaf(t, ncph, bxl);
                float y  = fmaf(t, nsph, byl);
                float fx = floorf(x);
                float fy = floorf(y);
                float wc = x - fx;
                float wr = y - fy;
                int addr = (int)fy * WSTR + (int)fx;
                float2 tp = __half22float2(smh[addr]);          // (v00, v01)
                float2 bt = __half22float2(smh[addr + WSTR]);   // (v10, v11)
                float top = fmaf(wc, tp.y - tp.x, tp.x);
                float bot = fmaf(wc, bt.y - bt.x, bt.x);
                acc = fmaf(wr, bot - top, acc + top);
            }
        }
    }

    // reduce 4 phases per detector
    acc += __shfl_xor_sync(0xFFFFFFFFu, acc, 1);
    acc += __shfl_xor_sync(0xFFFFFFFFu, acc, 2);

    if (sphase == 0) {
        g_part[a * N_DET + det] = acc;
    }
}

// ---------------------------------------------------------------------------
// Kernel 3a: square per ray, per-block tree reduce (double).
// ---------------------------------------------------------------------------
__global__ void raysum_kernel() {
    __shared__ double smr[256];
    const double hd_d = 208.0 * sqrt(2.0);
    const float  DTS  = (float)((2.0 * hd_d) / (N_SAMP - 1));
    int tid = threadIdx.x;
    int ray = blockIdx.x * 256 + tid;

    float val = g_part[ray] * DTS;
    smr[tid] = (double)val * (double)val;
    __syncthreads();
    for (int stride = 128; stride > 0; stride >>= 1) {
        if (tid < stride) smr[tid] += smr[tid + stride];
        __syncthreads();
    }
    if (tid == 0) g_blk[blockIdx.x] = smr[0];
}

// ---------------------------------------------------------------------------
// Kernel 3b: final deterministic reduction -> mean * SCALE.
// ---------------------------------------------------------------------------
__global__ void reduce_kernel(float* __restrict__ out) {
    __shared__ double smr[1024];
    int tid = threadIdx.x;
    smr[tid] = (tid < NBLK_R) ? g_blk[tid] : 0.0;
    __syncthreads();
    for (int stride = 512; stride > 0; stride >>= 1) {
        if (tid < stride) smr[tid] += smr[tid + stride];
        __syncthreads();
    }
    if (tid == 0) {
        const double SCALE = 512.0 / 416.0 * 0.03;
        out[0] = (float)(smr[0] / (double)NRAY * SCALE);
    }
}

// ---------------------------------------------------------------------------
extern "C" void kernel_launch(void* const* d_in, const int* in_sizes, int n_in,
                              void* d_out, int out_size) {
    const float* in  = (const float*)d_in[0];
    const float* tgt = (const float*)d_in[1];
    float* out = (float*)d_out;
    (void)in_sizes; (void)n_in; (void)out_size;

    static int configured = 0;
    if (!configured) {
        cudaFuncSetAttribute(ray_kernel,
                             cudaFuncAttributeMaxDynamicSharedMemorySize,
                             SMEM_BYTES);
        configured = 1;
    }

    pad_kernel<<<(PW * PW + 255) / 256, 256>>>(in, tgt);
    ray_kernel<<<dim3(NDG, NAG), 512, SMEM_BYTES>>>();
    raysum_kernel<<<NBLK_R, 256>>>();
    reduce_kernel<<<1, 1024>>>(out);
}